// round 7
// baseline (speedup 1.0000x reference)
#include <cuda_runtime.h>
#include <math.h>

#define BB   1024
#define TT   512
#define HH   64
#define ROWS 8
#define NTHR 512
#define IPITCH 68          // words per row in smem tiles (conflict-free padding)
#define TCH  8             // t-chunks for pre-GEMM
#define TPC  (TT / TCH)    // 64 timesteps per pre-GEMM CTA
#define LOG2E 1.4426950408889634f

// Scratch (static __device__ arrays are the allowed scratch mechanism)
__device__ float g_h1[(size_t)BB * TT * HH];     // layer-0 hidden sequence [B][T][H]
__device__ float g_pre[(size_t)BB * TT * 256];   // x-projection [cta][t][(j*8+r)*4+q]
__device__ float g_hlast[BB * HH];               // layer-1 final hidden state

__device__ __forceinline__ void fma2(unsigned long long &d,
                                     unsigned long long a, unsigned long long b) {
    asm("fma.rn.f32x2 %0, %1, %2, %0;" : "+l"(d) : "l"(a), "l"(b));
}
__device__ __forceinline__ float2 unpack2(unsigned long long v) {
    float2 f; asm("mov.b64 {%0, %1}, %2;" : "=f"(f.x), "=f"(f.y) : "l"(v)); return f;
}
__device__ __forceinline__ float ex2f(float x) {
    float r; asm("ex2.approx.f32 %0, %1;" : "=f"(r) : "f"(x)); return r;
}
__device__ __forceinline__ float rcpf(float x) {
    float r; asm("rcp.approx.f32 %0, %1;" : "=f"(r) : "f"(x)); return r;
}
__device__ __forceinline__ float fsig(float x) {
    return rcpf(1.0f + ex2f(-LOG2E * x));
}
__device__ __forceinline__ float ftanhf(float x) {
    return fmaf(rcpf(1.0f + ex2f(-2.0f * LOG2E * x)), 2.0f, -1.0f);
}

// ---------------------------------------------------------------------------
// pre[b][t][:] = bias + x[b][t] @ w_ih^T  (time-parallel)
// 512 threads = (j = tid>>3, r = tid&7); 2 timesteps per iteration for ILP.
// Output: g_pre[cta][t][(j*8+r)*4 + q] -> one STG.128 per (row, t).
// ---------------------------------------------------------------------------
__global__ void __launch_bounds__(NTHR, 1)
gemm_pre(const float* __restrict__ x_in,
         const float* __restrict__ w_ih,
         const float* __restrict__ b_ih, const float* __restrict__ b_hh,
         int x_is_scratch)
{
    extern __shared__ float sm[];
    float* wq = sm;                  // [16 kk][256 g][4 kp] = 16384 floats (64 KB)
    float* xb = sm + 16384;          // [2 tb][8 rows][IPITCH]

    const float* xp = x_is_scratch ? g_h1 : x_in;

    const int tid = threadIdx.x;
    const int j   = tid >> 3;        // unit 0..63
    const int r   = tid & 7;         // batch row 0..7
    const int row_base = blockIdx.x * ROWS;
    const int t0 = blockIdx.y * TPC;

    // stage w_ih gate-major: wq[kk*1024 + g*4 + kp], g = q*64 + j, k = kk*4+kp
    for (int idx = tid; idx < 64 * 256; idx += NTHR) {
        int kp = idx & 3;
        int g  = (idx >> 2) & 255;
        int kk = idx >> 10;
        wq[idx] = w_ih[g * 64 + kk * 4 + kp];
    }

    float bias[4];
    #pragma unroll
    for (int q = 0; q < 4; q++) bias[q] = b_ih[q * 64 + j] + b_hh[q * 64 + j];

    float* outp = g_pre + (size_t)blockIdx.x * TT * 2048;

    for (int it = 0; it < TPC / 2; it++) {
        int t = t0 + it * 2;
        __syncthreads();   // previous compute finished reading xb
        // load 2 x tiles (2 x 8 x 64 = 1024 elems, 512 threads x 2)
        #pragma unroll
        for (int e = 0; e < 2; e++) {
            int ii = tid + e * 512;
            int tb = ii >> 9, rem = ii & 511;
            int rr = rem >> 6, u = rem & 63;
            xb[(tb * 8 + rr) * IPITCH + u] =
                xp[((size_t)(row_base + rr) * TT + (t + tb)) * HH + u];
        }
        __syncthreads();

        unsigned long long acc[2][4];   // [tb][q]
        #pragma unroll
        for (int tb = 0; tb < 2; tb++)
            #pragma unroll
            for (int q = 0; q < 4; q++) acc[tb][q] = 0ull;

        const float* v0p = xb + r * IPITCH;
        const float* v1p = xb + (8 + r) * IPITCH;
        const float* wp  = wq + j * 4;

        #pragma unroll
        for (int kk = 0; kk < 16; kk++) {
            ulonglong2 v0 = *reinterpret_cast<const ulonglong2*>(v0p + kk * 4);
            ulonglong2 v1 = *reinterpret_cast<const ulonglong2*>(v1p + kk * 4);
            const float* wc = wp + kk * 1024;
            #pragma unroll
            for (int q = 0; q < 4; q++) {
                ulonglong2 w2 = *reinterpret_cast<const ulonglong2*>(wc + q * 256);
                fma2(acc[0][q], v0.x, w2.x);
                fma2(acc[0][q], v0.y, w2.y);
                fma2(acc[1][q], v1.x, w2.x);
                fma2(acc[1][q], v1.y, w2.y);
            }
        }

        #pragma unroll
        for (int tb = 0; tb < 2; tb++) {
            float4 st;
            float2 f0 = unpack2(acc[tb][0]);
            float2 f1 = unpack2(acc[tb][1]);
            float2 f2 = unpack2(acc[tb][2]);
            float2 f3 = unpack2(acc[tb][3]);
            st.x = f0.x + f0.y + bias[0];
            st.y = f1.x + f1.y + bias[1];
            st.z = f2.x + f2.y + bias[2];
            st.w = f3.x + f3.y + bias[3];
            *reinterpret_cast<float4*>(outp + (size_t)(t + tb) * 2048 + tid * 4) = st;
        }
    }
}

// ---------------------------------------------------------------------------
// Recurrent-only LSTM: gates = pre(t) + h @ w_hh^T  (K = 64).
// 512 threads = (j, r); thread computes all 4 gates of unit j for row r,
// c/h update thread-local. pre(t+1) prefetched via one LDG.128.
// ---------------------------------------------------------------------------
__global__ void __launch_bounds__(NTHR, 1)
lstm_rec(const float* __restrict__ w_hh, int store_seq, int store_last)
{
    extern __shared__ float sm[];
    float* wq = sm;                  // [16][256][4] = 16384 floats (64 KB)
    float* ib = sm + 16384;          // [2 buf][8 rows][IPITCH] (h only)

    const int tid = threadIdx.x;
    const int j   = tid >> 3;        // unit 0..63
    const int r   = tid & 7;         // batch row 0..7
    const int row_base = blockIdx.x * ROWS;

    // stage w_hh gate-major
    for (int idx = tid; idx < 64 * 256; idx += NTHR) {
        int kp = idx & 3;
        int g  = (idx >> 2) & 255;
        int kk = idx >> 10;
        wq[idx] = w_hh[g * 64 + kk * 4 + kp];
    }
    // init h buffer 0 = 0 (512 threads cover 8x64)
    {
        int rr = tid & 7, u = tid >> 3;
        ib[rr * IPITCH + u] = 0.0f;
    }

    const float* prep = g_pre + (size_t)blockIdx.x * TT * 2048 + tid * 4;

    float4 pcur = *reinterpret_cast<const float4*>(prep);   // pre(0)
    float cst = 0.0f;
    __syncthreads();

    int pb = 0;
    for (int t = 0; t < TT; t++) {
        // prefetch pre(t+1)
        int tn = (t + 1 < TT) ? (t + 1) : t;
        float4 pnext = *reinterpret_cast<const float4*>(prep + (size_t)tn * 2048);

        unsigned long long acc[4];
        #pragma unroll
        for (int q = 0; q < 4; q++) acc[q] = 0ull;

        const float* vp = ib + pb * (8 * IPITCH) + r * IPITCH;
        const float* wp = wq + j * 4;

        #pragma unroll
        for (int kk = 0; kk < 16; kk++) {
            ulonglong2 vv = *reinterpret_cast<const ulonglong2*>(vp + kk * 4);
            const float* wc = wp + kk * 1024;
            #pragma unroll
            for (int q = 0; q < 4; q++) {
                ulonglong2 w2 = *reinterpret_cast<const ulonglong2*>(wc + q * 256);
                fma2(acc[q], vv.x, w2.x);
                fma2(acc[q], vv.y, w2.y);
            }
        }

        float2 f0 = unpack2(acc[0]);
        float2 f1 = unpack2(acc[1]);
        float2 f2 = unpack2(acc[2]);
        float2 f3 = unpack2(acc[3]);
        float zi = f0.x + f0.y + pcur.x;
        float zf = f1.x + f1.y + pcur.y;
        float zg = f2.x + f2.y + pcur.z;
        float zo = f3.x + f3.y + pcur.w;

        float ig = fsig(zi), fg = fsig(zf), gg = ftanhf(zg), og = fsig(zo);
        cst = fg * cst + ig * gg;
        float h = og * ftanhf(cst);

        ib[(pb ^ 1) * (8 * IPITCH) + r * IPITCH + j] = h;

        if (store_seq)
            g_h1[((size_t)(row_base + r) * TT + t) * HH + j] = h;
        if (store_last && t == TT - 1)
            g_hlast[(row_base + r) * HH + j] = h;

        __syncthreads();
        pb ^= 1;
        pcur = pnext;
    }
}

// out[b][o] = softplus(h_last[b] . fc_w[o] + fc_b[o]),  O=32
__global__ void fc_softplus(const float* __restrict__ fc_w,
                            const float* __restrict__ fc_b,
                            float* __restrict__ out)
{
    __shared__ float wsh[64 * 32];
    __shared__ float bsh[32];
    const int tid = threadIdx.x;     // 128 threads

    for (int idx = tid; idx < 64 * 32; idx += 128) {
        int k = idx >> 5, o = idx & 31;
        wsh[idx] = fc_w[o * 64 + k];
    }
    if (tid < 32) bsh[tid] = fc_b[tid];
    __syncthreads();

    int gid = blockIdx.x * 128 + tid;
    int b = gid >> 5, o = gid & 31;
    const float* hr = g_hlast + b * 64;

    float z = bsh[o];
    #pragma unroll
    for (int k = 0; k < 64; k++)
        z += hr[k] * wsh[k * 32 + o];

    float r = (z > 20.0f) ? z : log1pf(__expf(z));
    out[gid] = r;
}

extern "C" void kernel_launch(void* const* d_in, const int* in_sizes, int n_in,
                              void* d_out, int out_size)
{
    (void)in_sizes; (void)n_in; (void)out_size;
    const float* x    = (const float*)d_in[0];
    const float* wih0 = (const float*)d_in[1];
    const float* whh0 = (const float*)d_in[2];
    const float* bih0 = (const float*)d_in[3];
    const float* bhh0 = (const float*)d_in[4];
    const float* wih1 = (const float*)d_in[5];
    const float* whh1 = (const float*)d_in[6];
    const float* bih1 = (const float*)d_in[7];
    const float* bhh1 = (const float*)d_in[8];
    const float* fcw  = (const float*)d_in[9];
    const float* fcb  = (const float*)d_in[10];
    float* out = (float*)d_out;

    const size_t smemA = (size_t)(16384 + 2 * ROWS * IPITCH) * sizeof(float);  // ~69.9 KB
    const size_t smemB = (size_t)(16384 + 2 * ROWS * IPITCH) * sizeof(float);
    cudaFuncSetAttribute(gemm_pre, cudaFuncAttributeMaxDynamicSharedMemorySize, (int)smemA);
    cudaFuncSetAttribute(lstm_rec, cudaFuncAttributeMaxDynamicSharedMemorySize, (int)smemB);

    dim3 pre_grid(BB / ROWS, TCH);

    // layer 0
    gemm_pre<<<pre_grid, NTHR, smemA>>>(x, wih0, bih0, bhh0, 0);
    lstm_rec<<<BB / ROWS, NTHR, smemB>>>(whh0, 1, 0);
    // layer 1 (input = g_h1)
    gemm_pre<<<pre_grid, NTHR, smemA>>>(nullptr, wih1, bih1, bhh1, 1);
    lstm_rec<<<BB / ROWS, NTHR, smemB>>>(whh1, 0, 1);
    // FC + softplus
    fc_softplus<<<(BB * 32) / 128, 128>>>(fcw, fcb, out);
}

// round 8
// speedup vs baseline: 1.3735x; 1.3735x over previous
#include <cuda_runtime.h>
#include <math.h>

#define BB   1024
#define TT   512
#define HH   64
#define ROWS 8
#define NTHR 256
#define IPITCH 68          // words per row in smem tiles (conflict-free padding)
#define TCH  16            // t-chunks for pre-GEMM
#define TPC  (TT / TCH)    // 32 timesteps per pre-GEMM CTA
#define LOG2E 1.4426950408889634f

// Scratch (static __device__ arrays are the allowed scratch mechanism)
__device__ float g_pre[(size_t)BB * TT * 256];   // layer-0 x-projection [cta][t][g][r]
__device__ float g_hlast[BB * HH];               // layer-1 final hidden state

__device__ __forceinline__ void fma2(unsigned long long &d,
                                     unsigned long long a, unsigned long long b) {
    asm("fma.rn.f32x2 %0, %1, %2, %0;" : "+l"(d) : "l"(a), "l"(b));
}
__device__ __forceinline__ float2 unpack2(unsigned long long v) {
    float2 f; asm("mov.b64 {%0, %1}, %2;" : "=f"(f.x), "=f"(f.y) : "l"(v)); return f;
}
__device__ __forceinline__ float ex2f(float x) {
    float r; asm("ex2.approx.f32 %0, %1;" : "=f"(r) : "f"(x)); return r;
}
__device__ __forceinline__ float rcpf(float x) {
    float r; asm("rcp.approx.f32 %0, %1;" : "=f"(r) : "f"(x)); return r;
}
__device__ __forceinline__ float fsig(float x) {
    return rcpf(1.0f + ex2f(-LOG2E * x));
}
__device__ __forceinline__ float ftanhf(float x) {
    return fmaf(rcpf(1.0f + ex2f(-2.0f * LOG2E * x)), 2.0f, -1.0f);
}

// ---------------------------------------------------------------------------
// pre0[b][t][g] = b_ih0[g]+b_hh0[g] + x[b][t] @ w_ih0[g]   (time-parallel)
// R4 tiling: thread (j=tid>>2, rg=tid&3) -> gates q=0..3 of unit j,
// rows 2rg, 2rg+1. Output g_pre[cta][t][(q*64+j)*8 + r] (float2 stores).
// ---------------------------------------------------------------------------
__global__ void __launch_bounds__(NTHR, 1)
gemm_pre(const float* __restrict__ x_in,
         const float* __restrict__ w_ih,
         const float* __restrict__ b_ih, const float* __restrict__ b_hh)
{
    extern __shared__ float sm[];
    float* wq = sm;                  // [16 kk][256 g][4 kp] = 16384 floats (64 KB)
    float* xb = sm + 16384;          // [8 rows][IPITCH]

    const int tid = threadIdx.x;
    const int j   = tid >> 2;
    const int rg  = tid & 3;
    const int r0  = rg * 2;
    const int row_base = blockIdx.x * ROWS;
    const int t0 = blockIdx.y * TPC;

    for (int idx = tid; idx < 64 * 256; idx += NTHR) {
        int kp = idx & 3;
        int g  = (idx >> 2) & 255;
        int kk = idx >> 10;
        wq[idx] = w_ih[g * 64 + kk * 4 + kp];
    }

    float bias[4];
    #pragma unroll
    for (int q = 0; q < 4; q++) bias[q] = b_ih[q * 64 + j] + b_hh[q * 64 + j];

    float* outp = g_pre + (size_t)blockIdx.x * TT * 2048;

    for (int t = t0; t < t0 + TPC; t++) {
        __syncthreads();
        #pragma unroll
        for (int e = 0; e < 2; e++) {
            int ii = tid + e * 256;
            int r = ii >> 6, u = ii & 63;
            xb[r * IPITCH + u] = x_in[((size_t)(row_base + r) * TT + t) * HH + u];
        }
        __syncthreads();

        unsigned long long acc[2][4];
        #pragma unroll
        for (int r = 0; r < 2; r++)
            #pragma unroll
            for (int q = 0; q < 4; q++) acc[r][q] = 0ull;

        const float* v0p = xb + r0 * IPITCH;
        const float* v1p = xb + (r0 + 1) * IPITCH;
        const float* wp  = wq + j * 4;

        #pragma unroll
        for (int kk = 0; kk < 16; kk++) {
            ulonglong2 v0 = *reinterpret_cast<const ulonglong2*>(v0p + kk * 4);
            ulonglong2 v1 = *reinterpret_cast<const ulonglong2*>(v1p + kk * 4);
            const float* wc = wp + kk * 1024;
            #pragma unroll
            for (int q = 0; q < 4; q++) {
                ulonglong2 w2 = *reinterpret_cast<const ulonglong2*>(wc + q * 256);
                fma2(acc[0][q], v0.x, w2.x);
                fma2(acc[0][q], v0.y, w2.y);
                fma2(acc[1][q], v1.x, w2.x);
                fma2(acc[1][q], v1.y, w2.y);
            }
        }

        float* ob = outp + (size_t)t * 2048;
        #pragma unroll
        for (int q = 0; q < 4; q++) {
            float2 f0 = unpack2(acc[0][q]);
            float2 f1 = unpack2(acc[1][q]);
            float2 st = make_float2(f0.x + f0.y + bias[q], f1.x + f1.y + bias[q]);
            *reinterpret_cast<float2*>(ob + (q * 64 + j) * 8 + r0) = st;
        }
    }
}

// ---------------------------------------------------------------------------
// Fused 2-layer recurrence. Per step t:
//   gates0 = pre0(t) + h1(t-1) @ w_hh0^T          -> h1(t)   (K=64)
//   gates1 = bias1 + h1(t) @ w_ih1^T + h2(t-1) @ w_hh1^T -> h2(t)  (K=64+64)
// 256 threads, thread (j, rg) owns gates of unit j for rows 2rg, 2rg+1;
// three gate-major 64KB weight tiles in SMEM (conflict-free: 1 wf/load).
// Layer-1's x-projection GEMM and the h1 gmem round-trip are eliminated.
// ---------------------------------------------------------------------------
__global__ void __launch_bounds__(NTHR, 1)
lstm_fused(const float* __restrict__ w_hh0,
           const float* __restrict__ w_ih1, const float* __restrict__ w_hh1,
           const float* __restrict__ b_ih1, const float* __restrict__ b_hh1)
{
    extern __shared__ float sm[];
    float* wq0  = sm;                 // w_hh0 gate-major, 16384 floats
    float* wq1i = sm + 16384;         // w_ih1 gate-major
    float* wq1h = sm + 32768;         // w_hh1 gate-major
    float* h1b  = sm + 49152;         // [2][8][IPITCH]
    float* h2b  = h1b + 2 * 8 * IPITCH;

    const int tid = threadIdx.x;
    const int j   = tid >> 2;
    const int rg  = tid & 3;
    const int r0  = rg * 2;
    const int row_base = blockIdx.x * ROWS;

    // ---- stage 3 weight tiles gate-major: w[kk*1024 + g*4 + kp]
    for (int idx = tid; idx < 3 * 16384; idx += NTHR) {
        int w  = idx >> 14;            // which tile
        int e  = idx & 16383;
        int kp = e & 3;
        int g  = (e >> 2) & 255;
        int kk = e >> 10;
        const float* src = (w == 0) ? w_hh0 : (w == 1) ? w_ih1 : w_hh1;
        sm[idx] = src[g * 64 + kk * 4 + kp];
    }
    // init h1, h2 buffers (buf 0) = 0
    #pragma unroll
    for (int e = 0; e < 2; e++) {
        int ii = tid + e * 256;
        int r = ii & 7, u = ii >> 3;
        h1b[r * IPITCH + u] = 0.0f;
        h2b[r * IPITCH + u] = 0.0f;
    }

    float bias1[4];
    #pragma unroll
    for (int q = 0; q < 4; q++) bias1[q] = b_ih1[q * 64 + j] + b_hh1[q * 64 + j];

    const float* prep = g_pre + (size_t)blockIdx.x * TT * 2048;
    float2 pcur[4];
    #pragma unroll
    for (int q = 0; q < 4; q++)
        pcur[q] = *reinterpret_cast<const float2*>(prep + (q * 64 + j) * 8 + r0);

    float c0a = 0.0f, c0b = 0.0f;   // layer-0 cell states (rows r0, r0+1)
    float c1a = 0.0f, c1b = 0.0f;   // layer-1 cell states
    const float* wp0  = wq0  + j * 4;
    const float* wp1i = wq1i + j * 4;
    const float* wp1h = wq1h + j * 4;

    __syncthreads();

    int pb = 0;
    for (int t = 0; t < TT; t++) {
        // prefetch pre0(t+1)
        int tn = (t + 1 < TT) ? (t + 1) : t;
        const float* pnb = prep + (size_t)tn * 2048;
        float2 pnext[4];
        #pragma unroll
        for (int q = 0; q < 4; q++)
            pnext[q] = *reinterpret_cast<const float2*>(pnb + (q * 64 + j) * 8 + r0);

        // ======== layer 0: gates0 = pre0(t) + h1(t-1) @ w_hh0^T ========
        unsigned long long acc[2][4];
        #pragma unroll
        for (int r = 0; r < 2; r++)
            #pragma unroll
            for (int q = 0; q < 4; q++) acc[r][q] = 0ull;

        {
            const float* v0p = h1b + pb * (8 * IPITCH) + r0 * IPITCH;
            const float* v1p = v0p + IPITCH;
            #pragma unroll
            for (int kk = 0; kk < 16; kk++) {
                ulonglong2 v0 = *reinterpret_cast<const ulonglong2*>(v0p + kk * 4);
                ulonglong2 v1 = *reinterpret_cast<const ulonglong2*>(v1p + kk * 4);
                const float* wc = wp0 + kk * 1024;
                #pragma unroll
                for (int q = 0; q < 4; q++) {
                    ulonglong2 w2 = *reinterpret_cast<const ulonglong2*>(wc + q * 256);
                    fma2(acc[0][q], v0.x, w2.x);
                    fma2(acc[0][q], v0.y, w2.y);
                    fma2(acc[1][q], v1.x, w2.x);
                    fma2(acc[1][q], v1.y, w2.y);
                }
            }
        }

        float z[2][4];
        #pragma unroll
        for (int q = 0; q < 4; q++) {
            float2 f0 = unpack2(acc[0][q]);
            float2 f1 = unpack2(acc[1][q]);
            z[0][q] = f0.x + f0.y + pcur[q].x;
            z[1][q] = f1.x + f1.y + pcur[q].y;
        }
        {
            float i0 = fsig(z[0][0]), f0 = fsig(z[0][1]), g0 = ftanhf(z[0][2]), o0 = fsig(z[0][3]);
            float i1 = fsig(z[1][0]), f1 = fsig(z[1][1]), g1 = ftanhf(z[1][2]), o1 = fsig(z[1][3]);
            c0a = f0 * c0a + i0 * g0;
            c0b = f1 * c0b + i1 * g1;
            float h0 = o0 * ftanhf(c0a);
            float h1 = o1 * ftanhf(c0b);
            float* nb = h1b + (pb ^ 1) * (8 * IPITCH);
            nb[r0 * IPITCH + j]       = h0;
            nb[(r0 + 1) * IPITCH + j] = h1;
        }
        __syncthreads();   // h1(t) complete

        // ======== layer 1: gates1 = bias1 + h1(t)@w_ih1^T + h2(t-1)@w_hh1^T ====
        #pragma unroll
        for (int r = 0; r < 2; r++)
            #pragma unroll
            for (int q = 0; q < 4; q++) acc[r][q] = 0ull;

        {
            const float* v0p = h1b + (pb ^ 1) * (8 * IPITCH) + r0 * IPITCH;
            const float* v1p = v0p + IPITCH;
            #pragma unroll
            for (int kk = 0; kk < 16; kk++) {
                ulonglong2 v0 = *reinterpret_cast<const ulonglong2*>(v0p + kk * 4);
                ulonglong2 v1 = *reinterpret_cast<const ulonglong2*>(v1p + kk * 4);
                const float* wc = wp1i + kk * 1024;
                #pragma unroll
                for (int q = 0; q < 4; q++) {
                    ulonglong2 w2 = *reinterpret_cast<const ulonglong2*>(wc + q * 256);
                    fma2(acc[0][q], v0.x, w2.x);
                    fma2(acc[0][q], v0.y, w2.y);
                    fma2(acc[1][q], v1.x, w2.x);
                    fma2(acc[1][q], v1.y, w2.y);
                }
            }
            const float* u0p = h2b + pb * (8 * IPITCH) + r0 * IPITCH;
            const float* u1p = u0p + IPITCH;
            #pragma unroll
            for (int kk = 0; kk < 16; kk++) {
                ulonglong2 v0 = *reinterpret_cast<const ulonglong2*>(u0p + kk * 4);
                ulonglong2 v1 = *reinterpret_cast<const ulonglong2*>(u1p + kk * 4);
                const float* wc = wp1h + kk * 1024;
                #pragma unroll
                for (int q = 0; q < 4; q++) {
                    ulonglong2 w2 = *reinterpret_cast<const ulonglong2*>(wc + q * 256);
                    fma2(acc[0][q], v0.x, w2.x);
                    fma2(acc[0][q], v0.y, w2.y);
                    fma2(acc[1][q], v1.x, w2.x);
                    fma2(acc[1][q], v1.y, w2.y);
                }
            }
        }

        #pragma unroll
        for (int q = 0; q < 4; q++) {
            float2 f0 = unpack2(acc[0][q]);
            float2 f1 = unpack2(acc[1][q]);
            z[0][q] = f0.x + f0.y + bias1[q];
            z[1][q] = f1.x + f1.y + bias1[q];
        }
        {
            float i0 = fsig(z[0][0]), f0 = fsig(z[0][1]), g0 = ftanhf(z[0][2]), o0 = fsig(z[0][3]);
            float i1 = fsig(z[1][0]), f1 = fsig(z[1][1]), g1 = ftanhf(z[1][2]), o1 = fsig(z[1][3]);
            c1a = f0 * c1a + i0 * g0;
            c1b = f1 * c1b + i1 * g1;
            float h0 = o0 * ftanhf(c1a);
            float h1 = o1 * ftanhf(c1b);
            float* nb = h2b + (pb ^ 1) * (8 * IPITCH);
            nb[r0 * IPITCH + j]       = h0;
            nb[(r0 + 1) * IPITCH + j] = h1;
            if (t == TT - 1) {
                g_hlast[(row_base + r0) * HH + j]     = h0;
                g_hlast[(row_base + r0 + 1) * HH + j] = h1;
            }
        }

        __syncthreads();
        pb ^= 1;
        #pragma unroll
        for (int q = 0; q < 4; q++) pcur[q] = pnext[q];
    }
}

// out[b][o] = softplus(h_last[b] . fc_w[o] + fc_b[o]),  O=32
__global__ void fc_softplus(const float* __restrict__ fc_w,
                            const float* __restrict__ fc_b,
                            float* __restrict__ out)
{
    __shared__ float wsh[64 * 32];
    __shared__ float bsh[32];
    const int tid = threadIdx.x;     // 128 threads

    for (int idx = tid; idx < 64 * 32; idx += 128) {
        int k = idx >> 5, o = idx & 31;
        wsh[idx] = fc_w[o * 64 + k];
    }
    if (tid < 32) bsh[tid] = fc_b[tid];
    __syncthreads();

    int gid = blockIdx.x * 128 + tid;
    int b = gid >> 5, o = gid & 31;
    const float* hr = g_hlast + b * 64;

    float z = bsh[o];
    #pragma unroll
    for (int k = 0; k < 64; k++)
        z += hr[k] * wsh[k * 32 + o];

    float r = (z > 20.0f) ? z : log1pf(__expf(z));
    out[gid] = r;
}

extern "C" void kernel_launch(void* const* d_in, const int* in_sizes, int n_in,
                              void* d_out, int out_size)
{
    (void)in_sizes; (void)n_in; (void)out_size;
    const float* x    = (const float*)d_in[0];
    const float* wih0 = (const float*)d_in[1];
    const float* whh0 = (const float*)d_in[2];
    const float* bih0 = (const float*)d_in[3];
    const float* bhh0 = (const float*)d_in[4];
    const float* wih1 = (const float*)d_in[5];
    const float* whh1 = (const float*)d_in[6];
    const float* bih1 = (const float*)d_in[7];
    const float* bhh1 = (const float*)d_in[8];
    const float* fcw  = (const float*)d_in[9];
    const float* fcb  = (const float*)d_in[10];
    float* out = (float*)d_out;

    const size_t smemA = (size_t)(16384 + ROWS * IPITCH) * sizeof(float);          // ~67.7 KB
    const size_t smemF = (size_t)(3 * 16384 + 4 * ROWS * IPITCH) * sizeof(float);  // ~201 KB
    cudaFuncSetAttribute(gemm_pre,   cudaFuncAttributeMaxDynamicSharedMemorySize, (int)smemA);
    cudaFuncSetAttribute(lstm_fused, cudaFuncAttributeMaxDynamicSharedMemorySize, (int)smemF);

    dim3 pre_grid(BB / ROWS, TCH);

    gemm_pre<<<pre_grid, NTHR, smemA>>>(x, wih0, bih0, bhh0);
    lstm_fused<<<BB / ROWS, NTHR, smemF>>>(whh0, wih1, whh1, bih1, bhh1);
    fc_softplus<<<(BB * 32) / 128, 128>>>(fcw, fcb, out);
}

// round 9
// speedup vs baseline: 1.4177x; 1.0322x over previous
#include <cuda_runtime.h>
#include <math.h>

#define BB   1024
#define TT   512
#define HH   64
#define ROWS 8
#define NTHR 256
#define IPITCH 68          // words per row in smem tiles (conflict-free padding)
#define TCH  16            // t-chunks for pre-GEMM
#define TPC  (TT / TCH)    // 32 timesteps per pre-GEMM CTA
#define LOG2E 1.4426950408889634f

// Scratch (static __device__ arrays are the allowed scratch mechanism)
__device__ float g_pre[(size_t)BB * TT * 256];   // layer-0 x-projection [cta][t][g][r]
__device__ float g_hlast[BB * HH];               // layer-1 final hidden state

__device__ __forceinline__ void fma2(unsigned long long &d,
                                     unsigned long long a, unsigned long long b) {
    asm("fma.rn.f32x2 %0, %1, %2, %0;" : "+l"(d) : "l"(a), "l"(b));
}
__device__ __forceinline__ float2 unpack2(unsigned long long v) {
    float2 f; asm("mov.b64 {%0, %1}, %2;" : "=f"(f.x), "=f"(f.y) : "l"(v)); return f;
}
__device__ __forceinline__ float ex2f(float x) {
    float r; asm("ex2.approx.f32 %0, %1;" : "=f"(r) : "f"(x)); return r;
}
__device__ __forceinline__ float rcpf(float x) {
    float r; asm("rcp.approx.f32 %0, %1;" : "=f"(r) : "f"(x)); return r;
}
__device__ __forceinline__ float fsig(float x) {
    return rcpf(1.0f + ex2f(-LOG2E * x));
}
__device__ __forceinline__ float ftanhf(float x) {
    return fmaf(rcpf(1.0f + ex2f(-2.0f * LOG2E * x)), 2.0f, -1.0f);
}

// ---------------------------------------------------------------------------
// pre0[b][t][g] = b_ih0[g]+b_hh0[g] + x[b][t] @ w_ih0[g]   (time-parallel)
// Thread (j=tid>>2, rg=tid&3) computes gates q=0..3 of unit j for rows
// 2rg,2rg+1 and TWO timesteps per iteration (weights amortized over 2t:
// per kk, 8 LDS.128 feed 32 FFMA2). Output g_pre[cta][t][(q*64+j)*8+r].
// ---------------------------------------------------------------------------
__global__ void __launch_bounds__(NTHR, 1)
gemm_pre(const float* __restrict__ x_in,
         const float* __restrict__ w_ih,
         const float* __restrict__ b_ih, const float* __restrict__ b_hh)
{
    extern __shared__ float sm[];
    float* wq = sm;                  // [16 kk][256 g][4 kp] = 16384 floats (64 KB)
    float* xb = sm + 16384;          // [2 tb][8 rows][IPITCH]

    const int tid = threadIdx.x;
    const int j   = tid >> 2;
    const int rg  = tid & 3;
    const int r0  = rg * 2;
    const int row_base = blockIdx.x * ROWS;
    const int t0 = blockIdx.y * TPC;

    for (int idx = tid; idx < 64 * 256; idx += NTHR) {
        int kp = idx & 3;
        int g  = (idx >> 2) & 255;
        int kk = idx >> 10;
        wq[idx] = w_ih[g * 64 + kk * 4 + kp];
    }

    float bias[4];
    #pragma unroll
    for (int q = 0; q < 4; q++) bias[q] = b_ih[q * 64 + j] + b_hh[q * 64 + j];

    float* outp = g_pre + (size_t)blockIdx.x * TT * 2048;

    for (int it = 0; it < TPC / 2; it++) {
        const int t = t0 + it * 2;
        __syncthreads();
        // load 2 timestep-tiles (2 x 8 x 64 = 1024 elems, 4 per thread)
        #pragma unroll
        for (int e = 0; e < 4; e++) {
            int ii = tid + e * 256;
            int tb = ii >> 9, rem = ii & 511;
            int r = rem >> 6, u = rem & 63;
            xb[(tb * 8 + r) * IPITCH + u] =
                x_in[((size_t)(row_base + r) * TT + (t + tb)) * HH + u];
        }
        __syncthreads();

        unsigned long long acc[2][2][4];   // [tb][row][q]
        #pragma unroll
        for (int tb = 0; tb < 2; tb++)
            #pragma unroll
            for (int r = 0; r < 2; r++)
                #pragma unroll
                for (int q = 0; q < 4; q++) acc[tb][r][q] = 0ull;

        const float* va = xb + r0 * IPITCH;            // t0, row r0
        const float* vb2 = va + IPITCH;                // t0, row r0+1
        const float* ua = xb + (8 + r0) * IPITCH;      // t1, row r0
        const float* ub = ua + IPITCH;                 // t1, row r0+1
        const float* wp = wq + j * 4;

        #pragma unroll
        for (int kk = 0; kk < 16; kk++) {
            ulonglong2 v0 = *reinterpret_cast<const ulonglong2*>(va  + kk * 4);
            ulonglong2 v1 = *reinterpret_cast<const ulonglong2*>(vb2 + kk * 4);
            ulonglong2 u0 = *reinterpret_cast<const ulonglong2*>(ua  + kk * 4);
            ulonglong2 u1 = *reinterpret_cast<const ulonglong2*>(ub  + kk * 4);
            const float* wc = wp + kk * 1024;
            #pragma unroll
            for (int q = 0; q < 4; q++) {
                ulonglong2 w2 = *reinterpret_cast<const ulonglong2*>(wc + q * 256);
                fma2(acc[0][0][q], v0.x, w2.x);
                fma2(acc[0][0][q], v0.y, w2.y);
                fma2(acc[0][1][q], v1.x, w2.x);
                fma2(acc[0][1][q], v1.y, w2.y);
                fma2(acc[1][0][q], u0.x, w2.x);
                fma2(acc[1][0][q], u0.y, w2.y);
                fma2(acc[1][1][q], u1.x, w2.x);
                fma2(acc[1][1][q], u1.y, w2.y);
            }
        }

        #pragma unroll
        for (int tb = 0; tb < 2; tb++) {
            float* ob = outp + (size_t)(t + tb) * 2048;
            #pragma unroll
            for (int q = 0; q < 4; q++) {
                float2 f0 = unpack2(acc[tb][0][q]);
                float2 f1 = unpack2(acc[tb][1][q]);
                float2 st = make_float2(f0.x + f0.y + bias[q], f1.x + f1.y + bias[q]);
                *reinterpret_cast<float2*>(ob + (q * 64 + j) * 8 + r0) = st;
            }
        }
    }
}

// ---------------------------------------------------------------------------
// Fused 2-layer recurrence. Per step t:
//   Phase A (one k-loop, TWO independent chains interleaved):
//     acc0 = h1(t-1) @ w_hh0^T      acc1 = h2(t-1) @ w_hh1^T
//   h1(t) from acc0 + pre0(t); store; barrier.
//   Phase B: acc1 += h1(t) @ w_ih1^T; h2(t) from acc1 + bias1; store; barrier.
// ---------------------------------------------------------------------------
__global__ void __launch_bounds__(NTHR, 1)
lstm_fused(const float* __restrict__ w_hh0,
           const float* __restrict__ w_ih1, const float* __restrict__ w_hh1,
           const float* __restrict__ b_ih1, const float* __restrict__ b_hh1)
{
    extern __shared__ float sm[];
    float* wq0  = sm;                 // w_hh0 gate-major, 16384 floats
    float* wq1i = sm + 16384;         // w_ih1 gate-major
    float* wq1h = sm + 32768;         // w_hh1 gate-major
    float* h1b  = sm + 49152;         // [2][8][IPITCH]
    float* h2b  = h1b + 2 * 8 * IPITCH;

    const int tid = threadIdx.x;
    const int j   = tid >> 2;
    const int rg  = tid & 3;
    const int r0  = rg * 2;
    const int row_base = blockIdx.x * ROWS;

    // ---- stage 3 weight tiles gate-major: w[kk*1024 + g*4 + kp]
    for (int idx = tid; idx < 3 * 16384; idx += NTHR) {
        int w  = idx >> 14;
        int e  = idx & 16383;
        int kp = e & 3;
        int g  = (e >> 2) & 255;
        int kk = e >> 10;
        const float* src = (w == 0) ? w_hh0 : (w == 1) ? w_ih1 : w_hh1;
        sm[idx] = src[g * 64 + kk * 4 + kp];
    }
    // init h1, h2 buffers (buf 0) = 0
    #pragma unroll
    for (int e = 0; e < 2; e++) {
        int ii = tid + e * 256;
        int r = ii & 7, u = ii >> 3;
        h1b[r * IPITCH + u] = 0.0f;
        h2b[r * IPITCH + u] = 0.0f;
    }

    float bias1[4];
    #pragma unroll
    for (int q = 0; q < 4; q++) bias1[q] = b_ih1[q * 64 + j] + b_hh1[q * 64 + j];

    const float* prep = g_pre + (size_t)blockIdx.x * TT * 2048;
    float2 pcur[4];
    #pragma unroll
    for (int q = 0; q < 4; q++)
        pcur[q] = *reinterpret_cast<const float2*>(prep + (q * 64 + j) * 8 + r0);

    float c0a = 0.0f, c0b = 0.0f;   // layer-0 cell states (rows r0, r0+1)
    float c1a = 0.0f, c1b = 0.0f;   // layer-1 cell states
    const float* wp0  = wq0  + j * 4;
    const float* wp1i = wq1i + j * 4;
    const float* wp1h = wq1h + j * 4;

    __syncthreads();

    int pb = 0;
    for (int t = 0; t < TT; t++) {
        // prefetch pre0(t+1)
        int tn = (t + 1 < TT) ? (t + 1) : t;
        const float* pnb = prep + (size_t)tn * 2048;
        float2 pnext[4];
        #pragma unroll
        for (int q = 0; q < 4; q++)
            pnext[q] = *reinterpret_cast<const float2*>(pnb + (q * 64 + j) * 8 + r0);

        // ======== Phase A: two independent matvecs, interleaved ========
        unsigned long long acc0[2][4], acc1[2][4];
        #pragma unroll
        for (int r = 0; r < 2; r++)
            #pragma unroll
            for (int q = 0; q < 4; q++) { acc0[r][q] = 0ull; acc1[r][q] = 0ull; }

        {
            const float* v0p = h1b + pb * (8 * IPITCH) + r0 * IPITCH;
            const float* v1p = v0p + IPITCH;
            const float* u0p = h2b + pb * (8 * IPITCH) + r0 * IPITCH;
            const float* u1p = u0p + IPITCH;
            #pragma unroll
            for (int kk = 0; kk < 16; kk++) {
                ulonglong2 v0 = *reinterpret_cast<const ulonglong2*>(v0p + kk * 4);
                ulonglong2 v1 = *reinterpret_cast<const ulonglong2*>(v1p + kk * 4);
                ulonglong2 u0 = *reinterpret_cast<const ulonglong2*>(u0p + kk * 4);
                ulonglong2 u1 = *reinterpret_cast<const ulonglong2*>(u1p + kk * 4);
                const float* wc0 = wp0  + kk * 1024;
                const float* wc1 = wp1h + kk * 1024;
                #pragma unroll
                for (int q = 0; q < 4; q++) {
                    ulonglong2 wA = *reinterpret_cast<const ulonglong2*>(wc0 + q * 256);
                    ulonglong2 wB = *reinterpret_cast<const ulonglong2*>(wc1 + q * 256);
                    fma2(acc0[0][q], v0.x, wA.x);
                    fma2(acc0[0][q], v0.y, wA.y);
                    fma2(acc0[1][q], v1.x, wA.x);
                    fma2(acc0[1][q], v1.y, wA.y);
                    fma2(acc1[0][q], u0.x, wB.x);
                    fma2(acc1[0][q], u0.y, wB.y);
                    fma2(acc1[1][q], u1.x, wB.x);
                    fma2(acc1[1][q], u1.y, wB.y);
                }
            }
        }

        // ---- layer-0 update -> h1(t)
        {
            float z[2][4];
            #pragma unroll
            for (int q = 0; q < 4; q++) {
                float2 f0 = unpack2(acc0[0][q]);
                float2 f1 = unpack2(acc0[1][q]);
                z[0][q] = f0.x + f0.y + pcur[q].x;
                z[1][q] = f1.x + f1.y + pcur[q].y;
            }
            float i0 = fsig(z[0][0]), f0 = fsig(z[0][1]), g0 = ftanhf(z[0][2]), o0 = fsig(z[0][3]);
            float i1 = fsig(z[1][0]), f1 = fsig(z[1][1]), g1 = ftanhf(z[1][2]), o1 = fsig(z[1][3]);
            c0a = f0 * c0a + i0 * g0;
            c0b = f1 * c0b + i1 * g1;
            float h0 = o0 * ftanhf(c0a);
            float h1 = o1 * ftanhf(c0b);
            float* nb = h1b + (pb ^ 1) * (8 * IPITCH);
            nb[r0 * IPITCH + j]       = h0;
            nb[(r0 + 1) * IPITCH + j] = h1;
        }
        __syncthreads();   // h1(t) complete

        // ======== Phase B: acc1 += h1(t) @ w_ih1^T ========
        {
            const float* v0p = h1b + (pb ^ 1) * (8 * IPITCH) + r0 * IPITCH;
            const float* v1p = v0p + IPITCH;
            #pragma unroll
            for (int kk = 0; kk < 16; kk++) {
                ulonglong2 v0 = *reinterpret_cast<const ulonglong2*>(v0p + kk * 4);
                ulonglong2 v1 = *reinterpret_cast<const ulonglong2*>(v1p + kk * 4);
                const float* wc = wp1i + kk * 1024;
                #pragma unroll
                for (int q = 0; q < 4; q++) {
                    ulonglong2 w2 = *reinterpret_cast<const ulonglong2*>(wc + q * 256);
                    fma2(acc1[0][q], v0.x, w2.x);
                    fma2(acc1[0][q], v0.y, w2.y);
                    fma2(acc1[1][q], v1.x, w2.x);
                    fma2(acc1[1][q], v1.y, w2.y);
                }
            }
        }

        // ---- layer-1 update -> h2(t)
        {
            float z[2][4];
            #pragma unroll
            for (int q = 0; q < 4; q++) {
                float2 f0 = unpack2(acc1[0][q]);
                float2 f1 = unpack2(acc1[1][q]);
                z[0][q] = f0.x + f0.y + bias1[q];
                z[1][q] = f1.x + f1.y + bias1[q];
            }
            float i0 = fsig(z[0][0]), f0 = fsig(z[0][1]), g0 = ftanhf(z[0][2]), o0 = fsig(z[0][3]);
            float i1 = fsig(z[1][0]), f1 = fsig(z[1][1]), g1 = ftanhf(z[1][2]), o1 = fsig(z[1][3]);
            c1a = f0 * c1a + i0 * g0;
            c1b = f1 * c1b + i1 * g1;
            float h0 = o0 * ftanhf(c1a);
            float h1 = o1 * ftanhf(c1b);
            float* nb = h2b + (pb ^ 1) * (8 * IPITCH);
            nb[r0 * IPITCH + j]       = h0;
            nb[(r0 + 1) * IPITCH + j] = h1;
            if (t == TT - 1) {
                g_hlast[(row_base + r0) * HH + j]     = h0;
                g_hlast[(row_base + r0 + 1) * HH + j] = h1;
            }
        }

        __syncthreads();
        pb ^= 1;
        #pragma unroll
        for (int q = 0; q < 4; q++) pcur[q] = pnext[q];
    }
}

// out[b][o] = softplus(h_last[b] . fc_w[o] + fc_b[o]),  O=32
__global__ void fc_softplus(const float* __restrict__ fc_w,
                            const float* __restrict__ fc_b,
                            float* __restrict__ out)
{
    __shared__ float wsh[64 * 32];
    __shared__ float bsh[32];
    const int tid = threadIdx.x;     // 128 threads

    for (int idx = tid; idx < 64 * 32; idx += 128) {
        int k = idx >> 5, o = idx & 31;
        wsh[idx] = fc_w[o * 64 + k];
    }
    if (tid < 32) bsh[tid] = fc_b[tid];
    __syncthreads();

    int gid = blockIdx.x * 128 + tid;
    int b = gid >> 5, o = gid & 31;
    const float* hr = g_hlast + b * 64;

    float z = bsh[o];
    #pragma unroll
    for (int k = 0; k < 64; k++)
        z += hr[k] * wsh[k * 32 + o];

    float r = (z > 20.0f) ? z : log1pf(__expf(z));
    out[gid] = r;
}

extern "C" void kernel_launch(void* const* d_in, const int* in_sizes, int n_in,
                              void* d_out, int out_size)
{
    (void)in_sizes; (void)n_in; (void)out_size;
    const float* x    = (const float*)d_in[0];
    const float* wih0 = (const float*)d_in[1];
    const float* whh0 = (const float*)d_in[2];
    const float* bih0 = (const float*)d_in[3];
    const float* bhh0 = (const float*)d_in[4];
    const float* wih1 = (const float*)d_in[5];
    const float* whh1 = (const float*)d_in[6];
    const float* bih1 = (const float*)d_in[7];
    const float* bhh1 = (const float*)d_in[8];
    const float* fcw  = (const float*)d_in[9];
    const float* fcb  = (const float*)d_in[10];
    float* out = (float*)d_out;

    const size_t smemA = (size_t)(16384 + 2 * ROWS * IPITCH) * sizeof(float);      // ~69.9 KB
    const size_t smemF = (size_t)(3 * 16384 + 4 * ROWS * IPITCH) * sizeof(float);  // ~201 KB
    cudaFuncSetAttribute(gemm_pre,   cudaFuncAttributeMaxDynamicSharedMemorySize, (int)smemA);
    cudaFuncSetAttribute(lstm_fused, cudaFuncAttributeMaxDynamicSharedMemorySize, (int)smemF);

    dim3 pre_grid(BB / ROWS, TCH);

    gemm_pre<<<pre_grid, NTHR, smemA>>>(x, wih0, bih0, bhh0);
    lstm_fused<<<BB / ROWS, NTHR, smemF>>>(whh0, wih1, whh1, bih1, bhh1);
    fc_softplus<<<(BB * 32) / 128, 128>>>(fcw, fcb, out);
}

// round 10
// speedup vs baseline: 1.4401x; 1.0158x over previous
#include <cuda_runtime.h>
#include <math.h>

#define BB   1024
#define TT   512
#define HH   64
#define ROWS 8
#define NTHR 256
#define FTHR 512           // fused kernel threads
#define IPITCH 68          // words per row in smem tiles (conflict-free padding)
#define TCH  16            // t-chunks for pre-GEMM
#define TPC  (TT / TCH)    // 32 timesteps per pre-GEMM CTA
#define LOG2E 1.4426950408889634f

// Scratch (static __device__ arrays are the allowed scratch mechanism)
__device__ float g_pre[(size_t)BB * TT * 256];   // layer-0 x-projection [cta][t][g][r]
__device__ float g_hlast[BB * HH];               // layer-1 final hidden state

__device__ __forceinline__ void fma2(unsigned long long &d,
                                     unsigned long long a, unsigned long long b) {
    asm("fma.rn.f32x2 %0, %1, %2, %0;" : "+l"(d) : "l"(a), "l"(b));
}
__device__ __forceinline__ float2 unpack2(unsigned long long v) {
    float2 f; asm("mov.b64 {%0, %1}, %2;" : "=f"(f.x), "=f"(f.y) : "l"(v)); return f;
}
__device__ __forceinline__ float ex2f(float x) {
    float r; asm("ex2.approx.f32 %0, %1;" : "=f"(r) : "f"(x)); return r;
}
__device__ __forceinline__ float rcpf(float x) {
    float r; asm("rcp.approx.f32 %0, %1;" : "=f"(r) : "f"(x)); return r;
}
__device__ __forceinline__ float fsig(float x) {
    return rcpf(1.0f + ex2f(-LOG2E * x));
}
__device__ __forceinline__ float ftanhf(float x) {
    return fmaf(rcpf(1.0f + ex2f(-2.0f * LOG2E * x)), 2.0f, -1.0f);
}

// ---------------------------------------------------------------------------
// pre0[b][t][g] = b_ih0[g]+b_hh0[g] + x[b][t] @ w_ih0[g]   (time-parallel)
// Thread (j=tid>>2, rg=tid&3): gates q=0..3 of unit j for rows 2rg,2rg+1,
// TWO timesteps per iteration. Output g_pre[cta][t][(q*64+j)*8+r].
// ---------------------------------------------------------------------------
__global__ void __launch_bounds__(NTHR, 1)
gemm_pre(const float* __restrict__ x_in,
         const float* __restrict__ w_ih,
         const float* __restrict__ b_ih, const float* __restrict__ b_hh)
{
    extern __shared__ float sm[];
    float* wq = sm;                  // [16 kk][256 g][4 kp] = 16384 floats (64 KB)
    float* xb = sm + 16384;          // [2 tb][8 rows][IPITCH]

    const int tid = threadIdx.x;
    const int j   = tid >> 2;
    const int rg  = tid & 3;
    const int r0  = rg * 2;
    const int row_base = blockIdx.x * ROWS;
    const int t0 = blockIdx.y * TPC;

    for (int idx = tid; idx < 64 * 256; idx += NTHR) {
        int kp = idx & 3;
        int g  = (idx >> 2) & 255;
        int kk = idx >> 10;
        wq[idx] = w_ih[g * 64 + kk * 4 + kp];
    }

    float bias[4];
    #pragma unroll
    for (int q = 0; q < 4; q++) bias[q] = b_ih[q * 64 + j] + b_hh[q * 64 + j];

    float* outp = g_pre + (size_t)blockIdx.x * TT * 2048;

    for (int it = 0; it < TPC / 2; it++) {
        const int t = t0 + it * 2;
        __syncthreads();
        #pragma unroll
        for (int e = 0; e < 4; e++) {
            int ii = tid + e * 256;
            int tb = ii >> 9, rem = ii & 511;
            int r = rem >> 6, u = rem & 63;
            xb[(tb * 8 + r) * IPITCH + u] =
                x_in[((size_t)(row_base + r) * TT + (t + tb)) * HH + u];
        }
        __syncthreads();

        unsigned long long acc[2][2][4];   // [tb][row][q]
        #pragma unroll
        for (int tb = 0; tb < 2; tb++)
            #pragma unroll
            for (int r = 0; r < 2; r++)
                #pragma unroll
                for (int q = 0; q < 4; q++) acc[tb][r][q] = 0ull;

        const float* va  = xb + r0 * IPITCH;
        const float* vb2 = va + IPITCH;
        const float* ua  = xb + (8 + r0) * IPITCH;
        const float* ub  = ua + IPITCH;
        const float* wp  = wq + j * 4;

        #pragma unroll
        for (int kk = 0; kk < 16; kk++) {
            ulonglong2 v0 = *reinterpret_cast<const ulonglong2*>(va  + kk * 4);
            ulonglong2 v1 = *reinterpret_cast<const ulonglong2*>(vb2 + kk * 4);
            ulonglong2 u0 = *reinterpret_cast<const ulonglong2*>(ua  + kk * 4);
            ulonglong2 u1 = *reinterpret_cast<const ulonglong2*>(ub  + kk * 4);
            const float* wc = wp + kk * 1024;
            #pragma unroll
            for (int q = 0; q < 4; q++) {
                ulonglong2 w2 = *reinterpret_cast<const ulonglong2*>(wc + q * 256);
                fma2(acc[0][0][q], v0.x, w2.x);
                fma2(acc[0][0][q], v0.y, w2.y);
                fma2(acc[0][1][q], v1.x, w2.x);
                fma2(acc[0][1][q], v1.y, w2.y);
                fma2(acc[1][0][q], u0.x, w2.x);
                fma2(acc[1][0][q], u0.y, w2.y);
                fma2(acc[1][1][q], u1.x, w2.x);
                fma2(acc[1][1][q], u1.y, w2.y);
            }
        }

        #pragma unroll
        for (int tb = 0; tb < 2; tb++) {
            float* ob = outp + (size_t)(t + tb) * 2048;
            #pragma unroll
            for (int q = 0; q < 4; q++) {
                float2 f0 = unpack2(acc[tb][0][q]);
                float2 f1 = unpack2(acc[tb][1][q]);
                float2 st = make_float2(f0.x + f0.y + bias[q], f1.x + f1.y + bias[q]);
                *reinterpret_cast<float2*>(ob + (q * 64 + j) * 8 + r0) = st;
            }
        }
    }
}

// ---------------------------------------------------------------------------
// Fused 2-layer recurrence, task-parallel warp groups (512 threads).
//   Group A (warps 0-7):  acc0 = h1(t-1)@w_hh0 ; h1(t) update; pre prefetch.
//   Group B (warps 8-15): acc1 = h2(t-1)@w_hh1 (phase 1, concurrent with A);
//                         after barrier: acc1 += h1(t)@w_ih1 ; h2(t) update.
// Both groups use the proven tiling: thread (j, rg) = 4 gates x 2 rows,
// gate-major weights (conflict-free), fp32x2 FFMA over k-parity.
// ---------------------------------------------------------------------------
__global__ void __launch_bounds__(FTHR, 1)
lstm_fused(const float* __restrict__ w_hh0,
           const float* __restrict__ w_ih1, const float* __restrict__ w_hh1,
           const float* __restrict__ b_ih1, const float* __restrict__ b_hh1)
{
    extern __shared__ float sm[];
    float* wq0  = sm;                 // w_hh0 gate-major, 16384 floats
    float* wq1i = sm + 16384;         // w_ih1 gate-major
    float* wq1h = sm + 32768;         // w_hh1 gate-major
    float* h1b  = sm + 49152;         // [2][8][IPITCH]
    float* h2b  = h1b + 2 * 8 * IPITCH;

    const int tid = threadIdx.x;
    const int lt  = tid & 255;        // index within group
    const bool gA = tid < 256;
    const int j   = lt >> 2;
    const int rg  = lt & 3;
    const int r0  = rg * 2;
    const int row_base = blockIdx.x * ROWS;

    // ---- stage 3 weight tiles gate-major: w[kk*1024 + g*4 + kp]
    for (int idx = tid; idx < 3 * 16384; idx += FTHR) {
        int w  = idx >> 14;
        int e  = idx & 16383;
        int kp = e & 3;
        int g  = (e >> 2) & 255;
        int kk = e >> 10;
        const float* src = (w == 0) ? w_hh0 : (w == 1) ? w_ih1 : w_hh1;
        sm[idx] = src[g * 64 + kk * 4 + kp];
    }
    // init h1, h2 buffers (buf 0) = 0 (512 threads cover 2*8*64)
    {
        int r = tid & 7, u = (tid >> 3) & 63;
        if (tid < 512) {
            if (tid < 256) h1b[r * IPITCH + ((tid >> 3) & 31) * 2 + 0] = 0.0f;
        }
    }
    // simpler: full coverage
    for (int ii = tid; ii < 2 * 8 * 64; ii += FTHR) {
        int half = ii >> 9, rem = ii & 511;
        int r = rem & 7, u = rem >> 3;
        (half == 0 ? h1b : h2b)[r * IPITCH + u] = 0.0f;
    }

    // group-specific setup
    float bias1[4];
    #pragma unroll
    for (int q = 0; q < 4; q++) bias1[q] = b_ih1[q * 64 + j] + b_hh1[q * 64 + j];

    const float* prep = g_pre + (size_t)blockIdx.x * TT * 2048;
    float2 pcur[4];
    if (gA) {
        #pragma unroll
        for (int q = 0; q < 4; q++)
            pcur[q] = *reinterpret_cast<const float2*>(prep + (q * 64 + j) * 8 + r0);
    }

    float ca = 0.0f, cb = 0.0f;       // cell states (A: layer 0, B: layer 1)
    const float* wp0  = wq0  + j * 4;
    const float* wp1i = wq1i + j * 4;
    const float* wp1h = wq1h + j * 4;

    __syncthreads();

    int pb = 0;
    for (int t = 0; t < TT; t++) {
        unsigned long long acc[2][4];
        #pragma unroll
        for (int r = 0; r < 2; r++)
            #pragma unroll
            for (int q = 0; q < 4; q++) acc[r][q] = 0ull;

        float2 pnext[4];

        if (gA) {
            // prefetch pre0(t+1)
            int tn = (t + 1 < TT) ? (t + 1) : t;
            const float* pnb = prep + (size_t)tn * 2048;
            #pragma unroll
            for (int q = 0; q < 4; q++)
                pnext[q] = *reinterpret_cast<const float2*>(pnb + (q * 64 + j) * 8 + r0);

            // acc0 = h1(t-1) @ w_hh0^T
            const float* v0p = h1b + pb * (8 * IPITCH) + r0 * IPITCH;
            const float* v1p = v0p + IPITCH;
            #pragma unroll
            for (int kk = 0; kk < 16; kk++) {
                ulonglong2 v0 = *reinterpret_cast<const ulonglong2*>(v0p + kk * 4);
                ulonglong2 v1 = *reinterpret_cast<const ulonglong2*>(v1p + kk * 4);
                const float* wc = wp0 + kk * 1024;
                #pragma unroll
                for (int q = 0; q < 4; q++) {
                    ulonglong2 w2 = *reinterpret_cast<const ulonglong2*>(wc + q * 256);
                    fma2(acc[0][q], v0.x, w2.x);
                    fma2(acc[0][q], v0.y, w2.y);
                    fma2(acc[1][q], v1.x, w2.x);
                    fma2(acc[1][q], v1.y, w2.y);
                }
            }

            // layer-0 update -> h1(t)
            float z[2][4];
            #pragma unroll
            for (int q = 0; q < 4; q++) {
                float2 f0 = unpack2(acc[0][q]);
                float2 f1 = unpack2(acc[1][q]);
                z[0][q] = f0.x + f0.y + pcur[q].x;
                z[1][q] = f1.x + f1.y + pcur[q].y;
            }
            float i0 = fsig(z[0][0]), f0 = fsig(z[0][1]), g0 = ftanhf(z[0][2]), o0 = fsig(z[0][3]);
            float i1 = fsig(z[1][0]), f1 = fsig(z[1][1]), g1 = ftanhf(z[1][2]), o1 = fsig(z[1][3]);
            ca = f0 * ca + i0 * g0;
            cb = f1 * cb + i1 * g1;
            float h0 = o0 * ftanhf(ca);
            float h1 = o1 * ftanhf(cb);
            float* nb = h1b + (pb ^ 1) * (8 * IPITCH);
            nb[r0 * IPITCH + j]       = h0;
            nb[(r0 + 1) * IPITCH + j] = h1;
        } else {
            // acc1 = h2(t-1) @ w_hh1^T
            const float* u0p = h2b + pb * (8 * IPITCH) + r0 * IPITCH;
            const float* u1p = u0p + IPITCH;
            #pragma unroll
            for (int kk = 0; kk < 16; kk++) {
                ulonglong2 v0 = *reinterpret_cast<const ulonglong2*>(u0p + kk * 4);
                ulonglong2 v1 = *reinterpret_cast<const ulonglong2*>(u1p + kk * 4);
                const float* wc = wp1h + kk * 1024;
                #pragma unroll
                for (int q = 0; q < 4; q++) {
                    ulonglong2 w2 = *reinterpret_cast<const ulonglong2*>(wc + q * 256);
                    fma2(acc[0][q], v0.x, w2.x);
                    fma2(acc[0][q], v0.y, w2.y);
                    fma2(acc[1][q], v1.x, w2.x);
                    fma2(acc[1][q], v1.y, w2.y);
                }
            }
        }

        __syncthreads();   // h1(t) visible to group B

        if (!gA) {
            // acc1 += h1(t) @ w_ih1^T
            const float* v0p = h1b + (pb ^ 1) * (8 * IPITCH) + r0 * IPITCH;
            const float* v1p = v0p + IPITCH;
            #pragma unroll
            for (int kk = 0; kk < 16; kk++) {
                ulonglong2 v0 = *reinterpret_cast<const ulonglong2*>(v0p + kk * 4);
                ulonglong2 v1 = *reinterpret_cast<const ulonglong2*>(v1p + kk * 4);
                const float* wc = wp1i + kk * 1024;
                #pragma unroll
                for (int q = 0; q < 4; q++) {
                    ulonglong2 w2 = *reinterpret_cast<const ulonglong2*>(wc + q * 256);
                    fma2(acc[0][q], v0.x, w2.x);
                    fma2(acc[0][q], v0.y, w2.y);
                    fma2(acc[1][q], v1.x, w2.x);
                    fma2(acc[1][q], v1.y, w2.y);
                }
            }

            // layer-1 update -> h2(t)
            float z[2][4];
            #pragma unroll
            for (int q = 0; q < 4; q++) {
                float2 f0 = unpack2(acc[0][q]);
                float2 f1 = unpack2(acc[1][q]);
                z[0][q] = f0.x + f0.y + bias1[q];
                z[1][q] = f1.x + f1.y + bias1[q];
            }
            float i0 = fsig(z[0][0]), f0 = fsig(z[0][1]), g0 = ftanhf(z[0][2]), o0 = fsig(z[0][3]);
            float i1 = fsig(z[1][0]), f1 = fsig(z[1][1]), g1 = ftanhf(z[1][2]), o1 = fsig(z[1][3]);
            ca = f0 * ca + i0 * g0;
            cb = f1 * cb + i1 * g1;
            float h0 = o0 * ftanhf(ca);
            float h1 = o1 * ftanhf(cb);
            float* nb = h2b + (pb ^ 1) * (8 * IPITCH);
            nb[r0 * IPITCH + j]       = h0;
            nb[(r0 + 1) * IPITCH + j] = h1;
            if (t == TT - 1) {
                g_hlast[(row_base + r0) * HH + j]     = h0;
                g_hlast[(row_base + r0 + 1) * HH + j] = h1;
            }
        } else {
            #pragma unroll
            for (int q = 0; q < 4; q++) pcur[q] = pnext[q];
        }

        __syncthreads();
        pb ^= 1;
    }
}

// out[b][o] = softplus(h_last[b] . fc_w[o] + fc_b[o]),  O=32
__global__ void fc_softplus(const float* __restrict__ fc_w,
                            const float* __restrict__ fc_b,
                            float* __restrict__ out)
{
    __shared__ float wsh[64 * 32];
    __shared__ float bsh[32];
    const int tid = threadIdx.x;     // 128 threads

    for (int idx = tid; idx < 64 * 32; idx += 128) {
        int k = idx >> 5, o = idx & 31;
        wsh[idx] = fc_w[o * 64 + k];
    }
    if (tid < 32) bsh[tid] = fc_b[tid];
    __syncthreads();

    int gid = blockIdx.x * 128 + tid;
    int b = gid >> 5, o = gid & 31;
    const float* hr = g_hlast + b * 64;

    float z = bsh[o];
    #pragma unroll
    for (int k = 0; k < 64; k++)
        z += hr[k] * wsh[k * 32 + o];

    float r = (z > 20.0f) ? z : log1pf(__expf(z));
    out[gid] = r;
}

extern "C" void kernel_launch(void* const* d_in, const int* in_sizes, int n_in,
                              void* d_out, int out_size)
{
    (void)in_sizes; (void)n_in; (void)out_size;
    const float* x    = (const float*)d_in[0];
    const float* wih0 = (const float*)d_in[1];
    const float* whh0 = (const float*)d_in[2];
    const float* bih0 = (const float*)d_in[3];
    const float* bhh0 = (const float*)d_in[4];
    const float* wih1 = (const float*)d_in[5];
    const float* whh1 = (const float*)d_in[6];
    const float* bih1 = (const float*)d_in[7];
    const float* bhh1 = (const float*)d_in[8];
    const float* fcw  = (const float*)d_in[9];
    const float* fcb  = (const float*)d_in[10];
    float* out = (float*)d_out;

    const size_t smemA = (size_t)(16384 + 2 * ROWS * IPITCH) * sizeof(float);      // ~69.9 KB
    const size_t smemF = (size_t)(3 * 16384 + 4 * ROWS * IPITCH) * sizeof(float);  // ~201 KB
    cudaFuncSetAttribute(gemm_pre,   cudaFuncAttributeMaxDynamicSharedMemorySize, (int)smemA);
    cudaFuncSetAttribute(lstm_fused, cudaFuncAttributeMaxDynamicSharedMemorySize, (int)smemF);

    dim3 pre_grid(BB / ROWS, TCH);

    gemm_pre<<<pre_grid, NTHR, smemA>>>(x, wih0, bih0, bhh0);
    lstm_fused<<<BB / ROWS, FTHR, smemF>>>(whh0, wih1, whh1, bih1, bhh1);
    fc_softplus<<<(BB * 32) / 128, 128>>>(fcw, fcb, out);
}